// round 1
// baseline (speedup 1.0000x reference)
#include <cuda_runtime.h>
#include <math.h>

#define N_REGS 32
#define KEY_DIM 128
#define BIT_WIDTH 64

// Precomputed output table: one 64-float row per idx value. 8 KB.
__device__ float g_table[N_REGS * BIT_WIDTH];

__device__ __forceinline__ float gelu_exact(float x) {
    // 0.5 * x * (1 + erf(x / sqrt(2)))  — matches jax.nn.gelu(approximate=False)
    return 0.5f * x * (1.0f + erff(x * 0.70710678118654752440f));
}

// One block per idx value (32 blocks, 128 threads each).
__global__ void build_table_kernel(
    const float* __restrict__ W1,        // [5, 128]
    const float* __restrict__ b1,        // [128]
    const float* __restrict__ W2,        // [128, 128]
    const float* __restrict__ b2,        // [128]
    const float* __restrict__ keys,      // [32, 128]
    const float* __restrict__ temperature, // scalar
    const float* __restrict__ rv)        // [32, 64]
{
    __shared__ float sh_h[KEY_DIM];
    __shared__ float sh_q[KEY_DIM];
    __shared__ float sh_attn[N_REGS];

    const int idx = blockIdx.x;
    const int tid = threadIdx.x;

    // h = gelu(bits @ W1 + b1)
    if (tid < KEY_DIM) {
        float acc = b1[tid];
        #pragma unroll
        for (int k = 0; k < 5; k++) {
            if ((idx >> k) & 1) acc += W1[k * KEY_DIM + tid];
        }
        sh_h[tid] = gelu_exact(acc);
    }
    __syncthreads();

    // query = h @ W2 + b2
    if (tid < KEY_DIM) {
        float q = b2[tid];
        #pragma unroll 8
        for (int j = 0; j < KEY_DIM; j++) {
            q = fmaf(sh_h[j], W2[j * KEY_DIM + tid], q);
        }
        sh_q[tid] = q;
    }
    __syncthreads();

    // sim[r] = query . keys[r]; softmax over 32 with clamped temperature
    if (tid < N_REGS) {
        float s = 0.0f;
        #pragma unroll 8
        for (int i = 0; i < KEY_DIM; i++) {
            s = fmaf(sh_q[i], keys[tid * KEY_DIM + i], s);
        }
        float temp = fmaxf(fabsf(temperature[0]), 0.1f);
        s = s / temp;
        // warp-level softmax over the 32 lanes
        float m = s;
        #pragma unroll
        for (int off = 16; off > 0; off >>= 1)
            m = fmaxf(m, __shfl_xor_sync(0xffffffffu, m, off));
        float e = expf(s - m);
        float sum = e;
        #pragma unroll
        for (int off = 16; off > 0; off >>= 1)
            sum += __shfl_xor_sync(0xffffffffu, sum, off);
        sh_attn[tid] = e / sum;
    }
    __syncthreads();

    // values = attn @ register_values; XZR (idx==31) reads zero
    if (tid < BIT_WIDTH) {
        float v = 0.0f;
        #pragma unroll
        for (int r = 0; r < N_REGS; r++) {
            v = fmaf(sh_attn[r], rv[r * BIT_WIDTH + tid], v);
        }
        if (idx == 31) v = 0.0f;
        g_table[idx * BIT_WIDTH + tid] = v;
    }
}

// Pure gather: out[b, :] = table[idx[b], :]. One float4 (16B) per thread,
// 16 threads per row. Table staged in shared memory (8 KB = 512 float4).
__global__ void gather_kernel(const int* __restrict__ idx,
                              float4* __restrict__ out,
                              int total_vec4)   // = B * 16
{
    __shared__ float4 stab[N_REGS * BIT_WIDTH / 4];  // 512

    const float4* gt = reinterpret_cast<const float4*>(g_table);
    for (int i = threadIdx.x; i < N_REGS * BIT_WIDTH / 4; i += blockDim.x)
        stab[i] = gt[i];
    __syncthreads();

    int t = blockIdx.x * blockDim.x + threadIdx.x;
    if (t >= total_vec4) return;

    int row = t >> 4;       // which of the B rows
    int c   = t & 15;       // which float4 within the 64-float row
    int r   = idx[row];     // broadcast within each 16-thread group (L1 hit)
    out[t] = stab[(r << 4) + c];
}

extern "C" void kernel_launch(void* const* d_in, const int* in_sizes, int n_in,
                              void* d_out, int out_size)
{
    const int*   idx  = (const int*)  d_in[0];
    const float* W1   = (const float*)d_in[1];
    const float* b1   = (const float*)d_in[2];
    const float* W2   = (const float*)d_in[3];
    const float* b2   = (const float*)d_in[4];
    const float* keys = (const float*)d_in[5];
    const float* temp = (const float*)d_in[6];
    const float* rv   = (const float*)d_in[7];

    const int B = in_sizes[0];

    build_table_kernel<<<N_REGS, 128>>>(W1, b1, W2, b2, keys, temp, rv);

    const int total_vec4 = B * (BIT_WIDTH / 4);   // B * 16
    const int threads = 256;
    const int blocks = (total_vec4 + threads - 1) / threads;
    gather_kernel<<<blocks, threads>>>(idx, (float4*)d_out, total_vec4);
}

// round 2
// speedup vs baseline: 1.3791x; 1.3791x over previous
#include <cuda_runtime.h>
#include <math.h>

#define N_REGS 32
#define KEY_DIM 128
#define BIT_WIDTH 64
#define TAB_VEC4 (N_REGS * BIT_WIDTH / 4)   // 512

// Precomputed output table: one 64-float row per idx value. 8 KB.
__device__ float g_table[N_REGS * BIT_WIDTH];

__device__ __forceinline__ float gelu_exact(float x) {
    // 0.5 * x * (1 + erf(x / sqrt(2)))  — matches jax.nn.gelu(approximate=False)
    return 0.5f * x * (1.0f + erff(x * 0.70710678118654752440f));
}

// One block per idx value (32 blocks, 128 threads each).
__global__ void build_table_kernel(
    const float* __restrict__ W1,        // [5, 128]
    const float* __restrict__ b1,        // [128]
    const float* __restrict__ W2,        // [128, 128]
    const float* __restrict__ b2,        // [128]
    const float* __restrict__ keys,      // [32, 128]
    const float* __restrict__ temperature, // scalar
    const float* __restrict__ rv)        // [32, 64]
{
    __shared__ float sh_h[KEY_DIM];
    __shared__ float sh_q[KEY_DIM];
    __shared__ float sh_attn[N_REGS];

    const int idx = blockIdx.x;
    const int tid = threadIdx.x;

    // h = gelu(bits @ W1 + b1)
    if (tid < KEY_DIM) {
        float acc = b1[tid];
        #pragma unroll
        for (int k = 0; k < 5; k++) {
            if ((idx >> k) & 1) acc += W1[k * KEY_DIM + tid];
        }
        sh_h[tid] = gelu_exact(acc);
    }
    __syncthreads();

    // query = h @ W2 + b2   (coalesced across tid)
    if (tid < KEY_DIM) {
        float q = b2[tid];
        #pragma unroll 8
        for (int j = 0; j < KEY_DIM; j++) {
            q = fmaf(sh_h[j], W2[j * KEY_DIM + tid], q);
        }
        sh_q[tid] = q;
    }
    __syncthreads();

    // sim[r] = query . keys[r]; 4 threads per register row, shfl-reduce.
    {
        int r    = tid >> 2;         // 0..31
        int part = tid & 3;          // 0..3
        float s = 0.0f;
        #pragma unroll 8
        for (int i = part * 32; i < part * 32 + 32; i++) {
            s = fmaf(sh_q[i], keys[r * KEY_DIM + i], s);
        }
        // reduce the 4 partials within each group of 4 lanes
        s += __shfl_xor_sync(0xffffffffu, s, 1);
        s += __shfl_xor_sync(0xffffffffu, s, 2);
        if (part == 0) sh_attn[r] = s;   // temporarily hold sim
    }
    __syncthreads();

    // softmax over 32 (first warp)
    if (tid < N_REGS) {
        float temp = fmaxf(fabsf(temperature[0]), 0.1f);
        float s = sh_attn[tid] / temp;
        float m = s;
        #pragma unroll
        for (int off = 16; off > 0; off >>= 1)
            m = fmaxf(m, __shfl_xor_sync(0xffffffffu, m, off));
        float e = expf(s - m);
        float sum = e;
        #pragma unroll
        for (int off = 16; off > 0; off >>= 1)
            sum += __shfl_xor_sync(0xffffffffu, sum, off);
        sh_attn[tid] = e / sum;
    }
    __syncthreads();

    // values = attn @ register_values; XZR (idx==31) reads zero
    if (tid < BIT_WIDTH) {
        float v = 0.0f;
        #pragma unroll
        for (int r = 0; r < N_REGS; r++) {
            v = fmaf(sh_attn[r], rv[r * BIT_WIDTH + tid], v);
        }
        if (idx == 31) v = 0.0f;
        g_table[idx * BIT_WIDTH + tid] = v;
    }
}

// Persistent grid-stride gather with per-thread MLP=4.
// out[b, :] = table[idx[b], :]. 16 threads per 64-float row.
// Stride between a thread's consecutive elements is blockDim (256), which is
// 0 mod 16, so each thread's column c = t & 15 is constant -> stores stay
// coalesced across the warp and smem access pattern is conflict-free.
#define UNROLL 4

__global__ void __launch_bounds__(256) gather_kernel(
    const int* __restrict__ idx,
    float4* __restrict__ out,
    int total_vec4)   // = B * 16
{
    __shared__ float4 stab[TAB_VEC4];  // 8 KB

    const float4* gt = reinterpret_cast<const float4*>(g_table);
    for (int i = threadIdx.x; i < TAB_VEC4; i += blockDim.x)
        stab[i] = gt[i];
    __syncthreads();

    const int step = gridDim.x * blockDim.x;           // elements per sub-iter
    int base = blockIdx.x * blockDim.x + threadIdx.x;

    // main loop: full UNROLL batches
    for (; base + (UNROLL - 1) * step < total_vec4; base += UNROLL * step) {
        int r[UNROLL];
        // batch the latency-bound idx loads (independent -> MLP=UNROLL)
        #pragma unroll
        for (int u = 0; u < UNROLL; u++) {
            int t = base + u * step;
            r[u] = __ldg(&idx[t >> 4]);
        }
        float4 v[UNROLL];
        #pragma unroll
        for (int u = 0; u < UNROLL; u++) {
            int t = base + u * step;
            v[u] = stab[(r[u] << 4) + (t & 15)];
        }
        #pragma unroll
        for (int u = 0; u < UNROLL; u++) {
            out[base + u * step] = v[u];
        }
    }
    // tail
    for (; base < total_vec4; base += step) {
        int rr = __ldg(&idx[base >> 4]);
        out[base] = stab[(rr << 4) + (base & 15)];
    }
}

extern "C" void kernel_launch(void* const* d_in, const int* in_sizes, int n_in,
                              void* d_out, int out_size)
{
    const int*   idx  = (const int*)  d_in[0];
    const float* W1   = (const float*)d_in[1];
    const float* b1   = (const float*)d_in[2];
    const float* W2   = (const float*)d_in[3];
    const float* b2   = (const float*)d_in[4];
    const float* keys = (const float*)d_in[5];
    const float* temp = (const float*)d_in[6];
    const float* rv   = (const float*)d_in[7];

    const int B = in_sizes[0];

    build_table_kernel<<<N_REGS, 128>>>(W1, b1, W2, b2, keys, temp, rv);

    const int total_vec4 = B * (BIT_WIDTH / 4);   // B * 16
    const int threads = 256;
    const int blocks = 1184;                      // 148 SMs * 8 CTAs
    gather_kernel<<<blocks, threads>>>(idx, (float4*)d_out, total_vec4);
}